// round 14
// baseline (speedup 1.0000x reference)
#include <cuda_runtime.h>
#include <cuda_bf16.h>
#include <math.h>
#include <cstdint>

#define NB      4096
#define PAD     (NB / 2)
#define BATCH   8192
#define T       512
#define NWARP   (T / 32)          // 16
#define GRID_N  608               // 152 SMs * 4 CTAs/SM

#define PRE_BLK   16              // precompute blocks
#define PRE_THR   256             // threads per precompute block (1 elem each)

// Row-invariant precomputed data.
__device__ float          g_p[NB];             // sigmoid(logits)
__device__ __nv_bfloat16  g_lb[NB];            // logits (bf16)
__device__ float          g_Cpart[PRE_BLK];    // partial sums of log_sigmoid(-l)

// ---------------------------------------------------------------------------
// Precompute: 16 blocks x 256 threads, ONE element per thread (~20 instrs).
// Each block writes its partial C; no atomics, no reset needed (all state
// rewritten every launch). Trigger releases the PDL secondary early.
// ---------------------------------------------------------------------------
__global__ __launch_bounds__(PRE_THR)
void precompute_kernel(const float* __restrict__ logits) {
    __shared__ float s_red[PRE_THR / 32];
    const int tid = threadIdx.x;
    const int j   = blockIdx.x * PRE_THR + tid;       // 16*256 = 4096 elems

    float l = __ldg(&logits[j]);
    float p = 1.0f / (1.0f + __expf(-l));
    g_p[j]  = p;
    g_lb[j] = __float2bfloat16(l);

    // log_sigmoid(-l) = log(1-p); 1-p in [0.35,0.65] here -> __logf safe.
    float c = __logf(1.0f - p);
    #pragma unroll
    for (int o = 16; o; o >>= 1) c += __shfl_xor_sync(0xFFFFFFFFu, c, o);
    if ((tid & 31) == 0) s_red[tid >> 5] = c;
    __syncthreads();
    if (tid == 0) {
        float v = 0.0f;
        #pragma unroll
        for (int i = 0; i < PRE_THR / 32; i++) v += s_red[i];
        g_Cpart[blockIdx.x] = v;
    }
    __syncthreads();
    cudaTriggerProgrammaticLaunchCompletion();
}

// ---------------------------------------------------------------------------
// Main fused kernel: proven 42.5us loop. First row's u/shift loads issued
// BEFORE the grid-dependency sync (they don't depend on the table), so the
// DRAM latency overlaps the primary's tail.
// ---------------------------------------------------------------------------
__global__ __launch_bounds__(T, 4)
void fused_kernel(const float* __restrict__ u,
                  const int*   __restrict__ shift,
                  float*       __restrict__ masks,
                  float*       __restrict__ log_probs) {
    __shared__ __align__(16) unsigned char s_g[2][NB + 16];
    __shared__ float s_red[2][NWARP];

    const int tid  = threadIdx.x;
    const int lane = tid & 31;
    const int warp = tid >> 5;

    // ---- issue first-row loads before the PDL sync ---------------------------
    const int b0 = blockIdx.x;
    const float4* __restrict__ u4_0 = (const float4*)(u + (size_t)b0 * NB);
    float4 ua = __ldcs(&u4_0[tid]);
    float4 ub = __ldcs(&u4_0[tid + T]);
    int    sh0 = __ldg(&shift[b0]);

    // ---- wait for the table ---------------------------------------------------
    cudaGridDependencySynchronize();

    const float4* __restrict__ p4  = (const float4*)g_p;
    const uint2*  __restrict__ lb2 = (const uint2*)g_lb;

    // per-CTA sum of the 16 partial C values (L2-hit, one-time)
    float cC;
    {
        float v = 0.0f;
        #pragma unroll
        for (int i = 0; i < PRE_BLK; i++) v += g_Cpart[i];
        cC = v;
    }

    int buf = 0;
    int b   = b0;
    int sh  = sh0;
    while (b < BATCH) {
        float4 pa = p4[tid];
        float4 pb = p4[tid + T];
        uint2  la = lb2[tid];
        uint2  lb = lb2[tid + T];

        __nv_bfloat162 la0 = *reinterpret_cast<__nv_bfloat162*>(&la.x);
        __nv_bfloat162 la1 = *reinterpret_cast<__nv_bfloat162*>(&la.y);
        __nv_bfloat162 lb0 = *reinterpret_cast<__nv_bfloat162*>(&lb.x);
        __nv_bfloat162 lb1 = *reinterpret_cast<__nv_bfloat162*>(&lb.y);

        uint32_t wa = (ua.x < pa.x ? 0x01u      : 0u)
                    | (ua.y < pa.y ? 0x100u     : 0u)
                    | (ua.z < pa.z ? 0x10000u   : 0u)
                    | (ua.w < pa.w ? 0x1000000u : 0u);
        uint32_t wb = (ub.x < pb.x ? 0x01u      : 0u)
                    | (ub.y < pb.y ? 0x100u     : 0u)
                    | (ub.z < pb.z ? 0x10000u   : 0u)
                    | (ub.w < pb.w ? 0x1000000u : 0u);
        float acc = (ua.x < pa.x ? __low2float(la0)  : 0.0f)
                  + (ua.y < pa.y ? __high2float(la0) : 0.0f)
                  + (ua.z < pa.z ? __low2float(la1)  : 0.0f)
                  + (ua.w < pa.w ? __high2float(la1) : 0.0f)
                  + (ub.x < pb.x ? __low2float(lb0)  : 0.0f)
                  + (ub.y < pb.y ? __high2float(lb0) : 0.0f)
                  + (ub.z < pb.z ? __low2float(lb1)  : 0.0f)
                  + (ub.w < pb.w ? __high2float(lb1) : 0.0f);

        uint32_t* sw = (uint32_t*)&s_g[buf][0];
        sw[tid]     = wa;
        sw[tid + T] = wb;

        // ---- block reduction -> log_probs[b] --------------------------------
        #pragma unroll
        for (int o = 16; o; o >>= 1) acc += __shfl_xor_sync(0xFFFFFFFFu, acc, o);
        if (lane == 0) s_red[buf][warp] = acc;
        __syncthreads();
        if (warp == 0) {
            float v = (lane < NWARP) ? s_red[buf][lane] : 0.0f;
            #pragma unroll
            for (int o = 8; o; o >>= 1) v += __shfl_xor_sync(0xFFFFFFFFu, v, o);
            if (lane == 0) log_probs[b] = v + cC;
        }

        // ---- prefetch next row's u/shift (overlaps gather+store) -------------
        const int curSh = sh;
        const int bn = b + GRID_N;
        if (bn < BATCH) {
            const float4* __restrict__ u4n = (const float4*)(u + (size_t)bn * NB);
            ua = __ldcs(&u4n[tid]);
            ub = __ldcs(&u4n[tid + T]);
            sh = __ldg(&shift[bn]);
        }

        // ---- reflect-shift gather -> 2x STG.128 ------------------------------
        float4* __restrict__ out4 = (float4*)(masks + (size_t)b * NB);
        #pragma unroll
        for (int it = 0; it < 2; ++it) {
            const int idx  = tid + it * T;
            const int base = curSh + 4 * idx - PAD;
            float4 o4;
            if (base >= 0 && base <= NB - 4) {
                const int wi = base >> 2;
                uint32_t w0 = sw[wi], w1 = sw[wi + 1];        // wi+1 within padding
                uint32_t pk = __byte_perm(w0, w1, 0x3210 + (base & 3) * 0x1111);
                o4.x = __int_as_float((pk & 0xFFu)         * 0x3F800000u);
                o4.y = __int_as_float(((pk >> 8)  & 0xFFu) * 0x3F800000u);
                o4.z = __int_as_float(((pk >> 16) & 0xFFu) * 0x3F800000u);
                o4.w = __int_as_float(((pk >> 24) & 0xFFu) * 0x3F800000u);
            } else {
                float r[4];
                #pragma unroll
                for (int k = 0; k < 4; k++) {
                    int s = base + k;
                    s = (s < 0) ? -s : s;
                    s = (s >= NB) ? (2 * (NB - 1) - s) : s;
                    r[k] = (float)s_g[buf][s];
                }
                o4 = make_float4(r[0], r[1], r[2], r[3]);
            }
            __stcs(&out4[idx], o4);
        }

        b = bn;
        buf ^= 1;
    }
}

// ---------------------------------------------------------------------------
extern "C" void kernel_launch(void* const* d_in, const int* in_sizes, int n_in,
                              void* d_out, int out_size) {
    const float* logits = (const float*)d_in[0];   // (NB,)
    const float* u      = (const float*)d_in[1];   // (B, NB)
    const int*   shift  = (const int*)  d_in[2];   // (B,)

    float* masks     = (float*)d_out;                       // (B, 1, NB)
    float* log_probs = (float*)d_out + (size_t)BATCH * NB;  // (B,)

    precompute_kernel<<<PRE_BLK, PRE_THR>>>(logits);

    cudaLaunchConfig_t cfg = {};
    cfg.gridDim  = dim3(GRID_N, 1, 1);
    cfg.blockDim = dim3(T, 1, 1);
    cfg.dynamicSmemBytes = 0;
    cfg.stream = 0;
    cudaLaunchAttribute attr[1];
    attr[0].id = cudaLaunchAttributeProgrammaticStreamSerialization;
    attr[0].val.programmaticStreamSerializationAllowed = 1;
    cfg.attrs = attr;
    cfg.numAttrs = 1;
    cudaLaunchKernelEx(&cfg, fused_kernel, u, shift, masks, log_probs);
}